// round 16
// baseline (speedup 1.0000x reference)
#include <cuda_runtime.h>

#define IMG 256
#define NG 1024
#define PIX (1.0f/256.0f)
#define T_TH 1e-4f
#define QCUT 10.0f   // cull: quad > 10 => contribution < alpha*e^-5 (boundary-only)
#define NBLK 512     // 16 x 32 tiles of 16x8 px; ~3.5 blocks/SM, all resident

// Sorted + packed per-Gaussian data (device scratch, no allocs)
__device__ float4 g_cull[NG];  // mx, my, rad2, pad
__device__ float4 g_q[NG];     // c00', c01', c11', k'
__device__ float4 g_c[NG];     // cr, cg, cb, pad
__device__ unsigned long long g_bar;   // monotonic barrier counter (zero-init)

// ---------------------------------------------------------------------------
// Single fused kernel: 512 blocks x 128 threads, 16x8 tiles, all resident
// (~3.5 blocks/SM -> deeper per-SM averaging of the tile-cost distribution,
// which is the only lever that has moved the time since R12).
// Phase 0: each block preps 2 Gaussians (one warp each), device-wide barrier.
// Phase 1: per-tile cull+compact of all 1024 sorted Gaussians (8 per thread).
// Phase 2: branch-free composite, groups of 4, warp-uniform vote every 16.
// ---------------------------------------------------------------------------
__global__ void __launch_bounds__(128) fused_kernel(const float* __restrict__ mean,
                                                    const float* __restrict__ cov,
                                                    const float* __restrict__ color,
                                                    const float* __restrict__ alpha,
                                                    const float* __restrict__ depth,
                                                    const float* __restrict__ bg,
                                                    const float* __restrict__ topleft,
                                                    float* __restrict__ out) {
    __shared__ float4 sA[NG+8];        // mx, my, c00', c01'  (aliased by depths in phase 0)
    __shared__ float4 sB[NG+8];        // c11', k', cr, cg
    __shared__ float4 sC4[(NG+8)/4];   // cb, packed
    __shared__ int    sW[4];

    int tid  = threadIdx.x;
    int lane = tid & 31, warp = tid >> 5;

    // tile geometry + background prefetch (hides under barrier wait)
    int bx = blockIdx.x & 15, by = blockIdx.x >> 4;   // 16 x 32 tiles of 16x8
    float tlx = topleft[0], tly = topleft[1];
    int tx = tid & 15, ty = tid >> 4;                 // ty in 0..7
    int pi = ((by*8 + ty)*IMG + bx*16 + tx)*3;
    float bgr = bg[pi+0], bgg = bg[pi+1], bgb = bg[pi+2];

    // ================= Phase 0: prep (2 Gaussians per block, 1 warp each) ====
    {
        float4* sd4 = (float4*)sA;              // alias: 1024 depths = 4KB
        const float4* d4g = (const float4*)depth;
        sd4[tid]       = d4g[tid];
        sd4[tid + 128] = d4g[tid + 128];
        __syncthreads();

        if (warp < 2) {
            int gi = blockIdx.x*2 + warp;
            float di = ((const float*)sd4)[gi];
            int r = 0;
            #pragma unroll
            for (int k = 0; k < 8; k++) {
                float4 d = sd4[lane*8 + k];
                int j = (lane*8 + k)*4;
                r += (d.x < di) || (d.x == di && (j+0) < gi);
                r += (d.y < di) || (d.y == di && (j+1) < gi);
                r += (d.z < di) || (d.z == di && (j+2) < gi);
                r += (d.w < di) || (d.w == di && (j+3) < gi);
            }
            #pragma unroll
            for (int s = 16; s; s >>= 1) r += __shfl_xor_sync(0xffffffffu, r, s);

            if (lane == 0) {
                int rank = r;
                float a = cov[gi*4+0], b = cov[gi*4+1], c = cov[gi*4+2], d = cov[gi*4+3];
                float det = a*d - b*c;
                const float L2E = 1.4426950408889634f;
                float i00  = d / det;
                float i11  = a / det;
                float ioff = -(b + c) / det;
                float mx = mean[gi*2+0], my = mean[gi*2+1];
                float bs      = 0.5f*(b + c);
                float half_tr = 0.5f*(a + d);
                float disc    = sqrtf(0.25f*(a - d)*(a - d) + bs*bs);
                float al = alpha[gi];
                g_cull[rank] = make_float4(mx, my, QCUT*(half_tr + disc), 0.0f);
                g_q[rank]    = make_float4(-0.5f*L2E*i00, -0.5f*L2E*ioff, -0.5f*L2E*i11,
                                           __log2f(fmaxf(al, 1e-30f)));
                g_c[rank]    = make_float4(color[gi*3+0], color[gi*3+1], color[gi*3+2], 0.0f);
                __threadfence();                // release this Gaussian's record
            }
        }
        __syncthreads();

        // device-wide barrier (replay-safe; all 512 blocks resident: smem 37KB
        // allows 6 blocks/SM, worst SM holds 4 -> no deadlock)
        if (tid == 0) {
            unsigned long long ticket = atomicAdd(&g_bar, 1ULL);
            unsigned long long target = (ticket/NBLK + 1ULL) * NBLK;
            unsigned long long cur;
            do {
                asm volatile("ld.acquire.gpu.global.u64 %0, [%1];"
                             : "=l"(cur) : "l"(&g_bar));
            } while (cur < target);
        }
        __syncthreads();
    }

    // ================= Phase 1: cull + compact (8 Gaussians/thread) ==========
    float x0 = (bx*16 + 0.5f)*PIX - tlx;
    float x1 = (bx*16 + 15.5f)*PIX - tlx;
    float y0 = (by*8 + 0.5f)*PIX - tly;
    float y1 = (by*8 + 7.5f)*PIX - tly;

    int g0 = tid*8;
    unsigned m = 0;
    #pragma unroll
    for (int u = 0; u < 8; u++) {
        float4 cu = g_cull[g0+u];
        float cx = fminf(fmaxf(cu.x, x0), x1) - cu.x;
        float cy = fminf(fmaxf(cu.y, y0), y1) - cu.y;
        if (cx*cx + cy*cy <= cu.z) m |= (1u << u);
    }
    int cnt = __popc(m);
    int scan = cnt;
    #pragma unroll
    for (int d = 1; d < 32; d <<= 1) {
        int v = __shfl_up_sync(0xffffffffu, scan, d);
        if (lane >= d) scan += v;
    }
    if (lane == 31) sW[warp] = scan;
    __syncthreads();                             // warp totals
    int4 wv = *(const int4*)&sW[0];
    int ntot = wv.x + wv.y + wv.z + wv.w;
    int base = 0;
    if (warp > 0) base += wv.x;
    if (warp > 1) base += wv.y;
    if (warp > 2) base += wv.z;
    int pos = base + (scan - cnt);
    #pragma unroll
    for (int u = 0; u < 8; u++) {
        if (m & (1u << u)) {
            float4 cu = g_cull[g0+u];            // L1-hot reload
            float4 qv = g_q[g0+u];
            float4 cv = g_c[g0+u];
            sA[pos] = make_float4(cu.x, cu.y, qv.x, qv.y);
            sB[pos] = make_float4(qv.z, qv.w, cv.x, cv.y);
            ((float*)sC4)[pos] = cv.z;
            pos++;
        }
    }
    if (tid < 8) {                               // zero-alpha dummies (exact no-op)
        sA[ntot+tid] = make_float4(0.f, 0.f, 0.f, 0.f);
        sB[ntot+tid] = make_float4(0.f, -1e30f, 0.f, 0.f);
        ((float*)sC4)[ntot+tid] = 0.f;
    }
    __syncthreads();                             // list published
    int n = (ntot + 3) & ~3;

    // ================= Phase 2: branch-free composite ========================
    float px = (bx*16 + tx + 0.5f)*PIX - tlx;
    float py = (by*8 + ty + 0.5f)*PIX - tly;

    float T = 1.0f, cr = 0.0f, cg = 0.0f, cb = 0.0f;

    float4 A0 = sA[0], A1 = sA[1], A2 = sA[2], A3 = sA[3];
    float4 B0 = sB[0], B1 = sB[1], B2 = sB[2], B3 = sB[3];
    float4 Cv = sC4[0];

    #pragma unroll 1
    for (int i = 0; i < n; i += 4) {
        float4 nA0 = sA[i+4], nA1 = sA[i+5], nA2 = sA[i+6], nA3 = sA[i+7];
        float4 nB0 = sB[i+4], nB1 = sB[i+5], nB2 = sB[i+6], nB3 = sB[i+7];
        float4 nCv = sC4[i/4 + 1];

        float a0, a1, a2, a3;
        {
            float dx, dy, qd;
            dx = px - A0.x; dy = py - A0.y;
            qd = dx*(A0.z*dx + A0.w*dy) + (B0.x*dy*dy + B0.y);
            a0 = fminf(exp2f(qd), 0.99f);
            dx = px - A1.x; dy = py - A1.y;
            qd = dx*(A1.z*dx + A1.w*dy) + (B1.x*dy*dy + B1.y);
            a1 = fminf(exp2f(qd), 0.99f);
            dx = px - A2.x; dy = py - A2.y;
            qd = dx*(A2.z*dx + A2.w*dy) + (B2.x*dy*dy + B2.y);
            a2 = fminf(exp2f(qd), 0.99f);
            dx = px - A3.x; dy = py - A3.y;
            qd = dx*(A3.z*dx + A3.w*dy) + (B3.x*dy*dy + B3.y);
            a3 = fminf(exp2f(qd), 0.99f);
        }
        // unconditional exclusive-prefix T weights; post-threshold slop
        // telescopes to <= T_TH absolute — within error budget (R14-proven).
        float t0 = T;
        float t1 = t0 * (1.0f - a0);
        float t2 = t1 * (1.0f - a1);
        float t3 = t2 * (1.0f - a2);
        T        = t3 * (1.0f - a3);
        float w0 = a0*t0, w1 = a1*t1, w2 = a2*t2, w3 = a3*t3;
        cr = fmaf(w0, B0.z, cr); cg = fmaf(w0, B0.w, cg); cb = fmaf(w0, Cv.x, cb);
        cr = fmaf(w1, B1.z, cr); cg = fmaf(w1, B1.w, cg); cb = fmaf(w1, Cv.y, cb);
        cr = fmaf(w2, B2.z, cr); cg = fmaf(w2, B2.w, cg); cb = fmaf(w2, Cv.z, cb);
        cr = fmaf(w3, B3.z, cr); cg = fmaf(w3, B3.w, cg); cb = fmaf(w3, Cv.w, cb);

        A0 = nA0; A1 = nA1; A2 = nA2; A3 = nA3;
        B0 = nB0; B1 = nB1; B2 = nB2; B3 = nB3;
        Cv = nCv;

        // warp-uniform termination vote every 4th group (convergent)
        if (((i >> 2) & 3) == 3) {
            if (!__any_sync(0xffffffffu, T > T_TH)) break;
        }
    }

    out[pi+0] = cr + T*bgr;
    out[pi+1] = cg + T*bgg;
    out[pi+2] = cb + T*bgb;
}

extern "C" void kernel_launch(void* const* d_in, const int* in_sizes, int n_in,
                              void* d_out, int out_size) {
    const float* mean    = (const float*)d_in[0];
    const float* cov     = (const float*)d_in[1];
    const float* color   = (const float*)d_in[2];
    const float* alpha   = (const float*)d_in[3];
    const float* depth   = (const float*)d_in[4];
    const float* bg      = (const float*)d_in[5];
    const float* topleft = (const float*)d_in[6];

    fused_kernel<<<NBLK, 128>>>(mean, cov, color, alpha, depth,
                                bg, topleft, (float*)d_out);
}

// round 17
// speedup vs baseline: 1.0037x; 1.0037x over previous
#include <cuda_runtime.h>

#define IMG 256
#define NG 1024
#define PIX (1.0f/256.0f)
#define T_TH 1e-4f
#define QCUT 10.0f   // cull: quad > 10 => contribution < alpha*e^-5 (boundary-only)
#define NBLK 296     // persistent blocks, 2/SM, all resident in one wave
#define TILES 256    // 16 x 16 tiles of 16x16 px
#define TPL (TILES + NBLK)   // tickets consumed per launch (deterministic)

// Sorted + packed per-Gaussian data (device scratch, no allocs)
__device__ float4 g_cull[NG];  // mx, my, rad2, pad
__device__ float4 g_q[NG];     // c00', c01', c11', k'
__device__ float4 g_c[NG];     // cr, cg, cb, pad
__device__ unsigned long long g_bar;    // barrier counter (zero-init, monotonic)
__device__ unsigned long long g_work;   // tile ticket counter (zero-init, monotonic)

// ---------------------------------------------------------------------------
// Persistent fused kernel: 296 blocks x 256 threads (2/SM, all resident).
// Phase 0: blocks 0..255 prep 4 Gaussians each; device-wide barrier
//          (monotonic epoch counter -> graph-replay safe).
// Work loop: blocks pull 16x16 tiles from a monotonic ticket queue
//          (exactly TILES valid + NBLK terminating tickets per launch ->
//          deterministic across graph replays). Greedy stealing balances the
//          per-SM makespan that static placement left on the table.
// Per tile: cull+compact (4 Gaussians/thread) then branch-free composite.
// ---------------------------------------------------------------------------
__global__ void __launch_bounds__(256) fused_kernel(const float* __restrict__ mean,
                                                    const float* __restrict__ cov,
                                                    const float* __restrict__ color,
                                                    const float* __restrict__ alpha,
                                                    const float* __restrict__ depth,
                                                    const float* __restrict__ bg,
                                                    const float* __restrict__ topleft,
                                                    float* __restrict__ out) {
    __shared__ float4 sA[NG+8];        // mx, my, c00', c01'  (aliased by depths in phase 0)
    __shared__ float4 sB[NG+8];        // c11', k', cr, cg
    __shared__ float4 sC4[(NG+8)/4];   // cb, packed
    __shared__ int    sW[8];
    __shared__ int    sRank[4];
    __shared__ unsigned long long sEpoch;
    __shared__ int    sTile;

    int tid  = threadIdx.x;
    int lane = tid & 31, warp = tid >> 5;
    float tlx = topleft[0], tly = topleft[1];

    // ================= Phase 0: prep (blocks 0..255, 4 Gaussians each) =======
    {
        if (blockIdx.x < 256) {
            float4* sd4 = (float4*)sA;          // alias: 1024 depths = 4KB
            const float4* d4g = (const float4*)depth;
            sd4[tid] = d4g[tid];
            if (tid < 4) sRank[tid] = 0;
            __syncthreads();

            int sub = tid >> 6;                 // 0..3 (64 threads per Gaussian)
            int gi  = blockIdx.x*4 + sub;
            float di = ((const float*)sd4)[gi];
            int lo4 = (tid & 63) * 4;           // 16 floats per thread
            int r = 0;
            #pragma unroll
            for (int j4 = 0; j4 < 4; j4++) {
                float4 d = sd4[lo4 + j4];
                int j = (lo4 + j4) * 4;
                r += (d.x < di) || (d.x == di && (j+0) < gi);
                r += (d.y < di) || (d.y == di && (j+1) < gi);
                r += (d.z < di) || (d.z == di && (j+2) < gi);
                r += (d.w < di) || (d.w == di && (j+3) < gi);
            }
            #pragma unroll
            for (int s = 16; s; s >>= 1) r += __shfl_xor_sync(0xffffffffu, r, s);
            if (lane == 0) atomicAdd(&sRank[sub], r);
            __syncthreads();

            if ((tid & 63) == 0) {
                int rank = sRank[sub];
                float a = cov[gi*4+0], b = cov[gi*4+1], c = cov[gi*4+2], d = cov[gi*4+3];
                float det = a*d - b*c;
                const float L2E = 1.4426950408889634f;
                float i00  = d / det;
                float i11  = a / det;
                float ioff = -(b + c) / det;
                float mx = mean[gi*2+0], my = mean[gi*2+1];
                float bs      = 0.5f*(b + c);
                float half_tr = 0.5f*(a + d);
                float disc    = sqrtf(0.25f*(a - d)*(a - d) + bs*bs);
                float al = alpha[gi];
                g_cull[rank] = make_float4(mx, my, QCUT*(half_tr + disc), 0.0f);
                g_q[rank]    = make_float4(-0.5f*L2E*i00, -0.5f*L2E*ioff, -0.5f*L2E*i11,
                                           __log2f(fmaxf(al, 1e-30f)));
                g_c[rank]    = make_float4(color[gi*3+0], color[gi*3+1], color[gi*3+2], 0.0f);
                __threadfence();                // release this Gaussian's record
            }
        }
        __syncthreads();

        // device-wide barrier (replay-safe; all 296 blocks resident)
        if (tid == 0) {
            unsigned long long ticket = atomicAdd(&g_bar, 1ULL);
            unsigned long long target = (ticket/NBLK + 1ULL) * NBLK;
            sEpoch = ticket / NBLK;             // launch index
            unsigned long long cur;
            do {
                asm volatile("ld.acquire.gpu.global.u64 %0, [%1];"
                             : "=l"(cur) : "l"(&g_bar));
            } while (cur < target);
        }
        __syncthreads();
    }
    unsigned long long tbase = sEpoch * (unsigned long long)TPL;

    // ================= Work loop: steal tiles until queue drained ============
    while (true) {
        if (tid == 0) {
            unsigned long long t = atomicAdd(&g_work, 1ULL);
            sTile = (int)(t - tbase);
        }
        __syncthreads();                         // broadcast tile + protect smem
        int tile = sTile;
        if (tile >= TILES) break;

        int bx = tile & 15, by = tile >> 4;
        int tx = tid & 15, ty = tid >> 4;
        int pi = ((by*16 + ty)*IMG + bx*16 + tx)*3;
        float bgr = bg[pi+0], bgg = bg[pi+1], bgb = bg[pi+2];

        // ---- cull + compact (4 Gaussians/thread) ----
        float x0 = (bx*16 + 0.5f)*PIX - tlx;
        float x1 = (bx*16 + 15.5f)*PIX - tlx;
        float y0 = (by*16 + 0.5f)*PIX - tly;
        float y1 = (by*16 + 15.5f)*PIX - tly;

        int g0 = tid*4;
        float4 cu0 = g_cull[g0+0];
        float4 cu1 = g_cull[g0+1];
        float4 cu2 = g_cull[g0+2];
        float4 cu3 = g_cull[g0+3];
        unsigned m = 0;
        {
            float cx, cy;
            cx = fminf(fmaxf(cu0.x, x0), x1) - cu0.x;
            cy = fminf(fmaxf(cu0.y, y0), y1) - cu0.y;
            if (cx*cx + cy*cy <= cu0.z) m |= 1u;
            cx = fminf(fmaxf(cu1.x, x0), x1) - cu1.x;
            cy = fminf(fmaxf(cu1.y, y0), y1) - cu1.y;
            if (cx*cx + cy*cy <= cu1.z) m |= 2u;
            cx = fminf(fmaxf(cu2.x, x0), x1) - cu2.x;
            cy = fminf(fmaxf(cu2.y, y0), y1) - cu2.y;
            if (cx*cx + cy*cy <= cu2.z) m |= 4u;
            cx = fminf(fmaxf(cu3.x, x0), x1) - cu3.x;
            cy = fminf(fmaxf(cu3.y, y0), y1) - cu3.y;
            if (cx*cx + cy*cy <= cu3.z) m |= 8u;
        }
        int cnt = __popc(m);
        int scan = cnt;
        #pragma unroll
        for (int d = 1; d < 32; d <<= 1) {
            int v = __shfl_up_sync(0xffffffffu, scan, d);
            if (lane >= d) scan += v;
        }
        if (lane == 31) sW[warp] = scan;
        __syncthreads();                         // warp totals
        int4 wv0 = *(const int4*)&sW[0];
        int4 wv1 = *(const int4*)&sW[4];
        int ntot = (wv0.x + wv0.y + wv0.z + wv0.w) + (wv1.x + wv1.y + wv1.z + wv1.w);
        int base = 0;
        if (warp > 0) base += wv0.x;
        if (warp > 1) base += wv0.y;
        if (warp > 2) base += wv0.z;
        if (warp > 3) base += wv0.w;
        if (warp > 4) base += wv1.x;
        if (warp > 5) base += wv1.y;
        if (warp > 6) base += wv1.z;
        int pos = base + (scan - cnt);
        #pragma unroll
        for (int u = 0; u < 4; u++) {
            if (m & (1u << u)) {
                float4 cu = (u == 0) ? cu0 : (u == 1) ? cu1 : (u == 2) ? cu2 : cu3;
                float4 qv = g_q[g0+u];
                float4 cv = g_c[g0+u];
                sA[pos] = make_float4(cu.x, cu.y, qv.x, qv.y);
                sB[pos] = make_float4(qv.z, qv.w, cv.x, cv.y);
                ((float*)sC4)[pos] = cv.z;
                pos++;
            }
        }
        if (tid < 8) {                           // zero-alpha dummies (exact no-op)
            sA[ntot+tid] = make_float4(0.f, 0.f, 0.f, 0.f);
            sB[ntot+tid] = make_float4(0.f, -1e30f, 0.f, 0.f);
            ((float*)sC4)[ntot+tid] = 0.f;
        }
        __syncthreads();                         // list published
        int n = (ntot + 3) & ~3;

        // ---- branch-free composite ----
        float px = (bx*16 + tx + 0.5f)*PIX - tlx;
        float py = (by*16 + ty + 0.5f)*PIX - tly;

        float T = 1.0f, cr = 0.0f, cg = 0.0f, cb = 0.0f;

        float4 A0 = sA[0], A1 = sA[1], A2 = sA[2], A3 = sA[3];
        float4 B0 = sB[0], B1 = sB[1], B2 = sB[2], B3 = sB[3];
        float4 Cv = sC4[0];

        #pragma unroll 1
        for (int i = 0; i < n; i += 4) {
            float4 nA0 = sA[i+4], nA1 = sA[i+5], nA2 = sA[i+6], nA3 = sA[i+7];
            float4 nB0 = sB[i+4], nB1 = sB[i+5], nB2 = sB[i+6], nB3 = sB[i+7];
            float4 nCv = sC4[i/4 + 1];

            float a0, a1, a2, a3;
            {
                float dx, dy, qd;
                dx = px - A0.x; dy = py - A0.y;
                qd = dx*(A0.z*dx + A0.w*dy) + (B0.x*dy*dy + B0.y);
                a0 = fminf(exp2f(qd), 0.99f);
                dx = px - A1.x; dy = py - A1.y;
                qd = dx*(A1.z*dx + A1.w*dy) + (B1.x*dy*dy + B1.y);
                a1 = fminf(exp2f(qd), 0.99f);
                dx = px - A2.x; dy = py - A2.y;
                qd = dx*(A2.z*dx + A2.w*dy) + (B2.x*dy*dy + B2.y);
                a2 = fminf(exp2f(qd), 0.99f);
                dx = px - A3.x; dy = py - A3.y;
                qd = dx*(A3.z*dx + A3.w*dy) + (B3.x*dy*dy + B3.y);
                a3 = fminf(exp2f(qd), 0.99f);
            }
            float t0 = T;
            float t1 = t0 * (1.0f - a0);
            float t2 = t1 * (1.0f - a1);
            float t3 = t2 * (1.0f - a2);
            T        = t3 * (1.0f - a3);
            float w0 = a0*t0, w1 = a1*t1, w2 = a2*t2, w3 = a3*t3;
            cr = fmaf(w0, B0.z, cr); cg = fmaf(w0, B0.w, cg); cb = fmaf(w0, Cv.x, cb);
            cr = fmaf(w1, B1.z, cr); cg = fmaf(w1, B1.w, cg); cb = fmaf(w1, Cv.y, cb);
            cr = fmaf(w2, B2.z, cr); cg = fmaf(w2, B2.w, cg); cb = fmaf(w2, Cv.z, cb);
            cr = fmaf(w3, B3.z, cr); cg = fmaf(w3, B3.w, cg); cb = fmaf(w3, Cv.w, cb);

            A0 = nA0; A1 = nA1; A2 = nA2; A3 = nA3;
            B0 = nB0; B1 = nB1; B2 = nB2; B3 = nB3;
            Cv = nCv;

            // warp-uniform termination vote every 4th group (convergent)
            if (((i >> 2) & 3) == 3) {
                if (!__any_sync(0xffffffffu, T > T_TH)) break;
            }
        }

        out[pi+0] = cr + T*bgr;
        out[pi+1] = cg + T*bgg;
        out[pi+2] = cb + T*bgb;

        __syncthreads();                         // all reads of sA/sB done
    }
}

extern "C" void kernel_launch(void* const* d_in, const int* in_sizes, int n_in,
                              void* d_out, int out_size) {
    const float* mean    = (const float*)d_in[0];
    const float* cov     = (const float*)d_in[1];
    const float* color   = (const float*)d_in[2];
    const float* alpha   = (const float*)d_in[3];
    const float* depth   = (const float*)d_in[4];
    const float* bg      = (const float*)d_in[5];
    const float* topleft = (const float*)d_in[6];

    fused_kernel<<<NBLK, 256>>>(mean, cov, color, alpha, depth,
                                bg, topleft, (float*)d_out);
}